// round 11
// baseline (speedup 1.0000x reference)
#include <cuda_runtime.h>
#include <cuda_bf16.h>
#include <math.h>
#include <stdint.h>

// Problem constants
#define B_   256
#define T_   36
#define S_   96
#define D_   1024
#define H_   1024
#define L_   2
#define KCAT 2048
#define G3   (3 * H_)
#define BT   (B_ * T_)

// Output buffer layout (flattened tuple: output, hidden_f, attn_weights)
#define OUT_Y   ((size_t)0)
#define OUT_H   ((size_t)B_ * T_ * D_)
#define OUT_AW  (OUT_H + (size_t)L_ * B_ * H_)

typedef __nv_bfloat16 bf16;

// ---------------- static scratch (no allocations allowed) ------------------
__device__ float g_pattn[BT * S_];
__device__ float g_pcomb[BT * D_];
__device__ float g_gi0[B_ * G3];
__device__ float g_gh0[B_ * G3];
__device__ float g_gi1[B_ * G3];
__device__ float g_gh1[B_ * G3];

__device__ bf16 g_tgt_hi[BT * D_],   g_tgt_lo[BT * D_];
__device__ bf16 g_combx_hi[D_ * D_], g_combx_lo[D_ * D_];
__device__ bf16 g_combh_hi[D_ * D_], g_combh_lo[D_ * D_];
__device__ bf16 g_wih_hi[L_ * G3 * D_], g_wih_lo[L_ * G3 * D_];
__device__ bf16 g_whh_hi[L_ * G3 * H_], g_whh_lo[L_ * G3 * H_];
__device__ bf16 g_o1_hi[D_ * H_],  g_o1_lo[D_ * H_];
__device__ bf16 g_o2_hi[D_ * D_],  g_o2_lo[D_ * D_];
__device__ bf16 g_xc_hi[B_ * D_],  g_xc_lo[B_ * D_];
__device__ bf16 g_h0_hi[B_ * H_],  g_h0_lo[B_ * H_];
__device__ bf16 g_h1_hi[B_ * H_],  g_h1_lo[B_ * H_];
__device__ bf16 g_we_hi[B_ * H_],  g_we_lo[B_ * H_];
__device__ bf16 g_hseq_hi[BT * H_], g_hseq_lo[BT * H_];
__device__ bf16 g_y_hi[BT * D_],   g_y_lo[BT * D_];

// Grid barrier state (monotonic generation -> graph-replay safe)
__device__ unsigned g_cnt = 0;
__device__ unsigned g_gen = 0;

// ---------------------------------------------------------------------------
__device__ __forceinline__ void split1(float x, bf16& h, bf16& l) {
    h = __float2bfloat16(x);
    l = __float2bfloat16(x - __bfloat162float(h));
}
__device__ __forceinline__ float sigmoidf_(float x) { return 1.f / (1.f + expf(-x)); }

__global__ void split_kernel(const float* __restrict__ src, int srcld, int srcoff,
                             int cols, bf16* __restrict__ hi, bf16* __restrict__ lo,
                             int n)
{
    int i = blockIdx.x * 256 + threadIdx.x;
    if (i >= n) return;
    int r = i / cols, c = i - r * cols;
    float x = src[(size_t)r * srcld + srcoff + c];
    bf16 h, l; split1(x, h, l);
    hi[i] = h; lo[i] = l;
}

// ---------------------------------------------------------------------------
// Tensor-core GEMM tile: bf16 hi/lo 3-term split, fp32 accumulate.
// CTA tile 128x64, 256 threads (8 warps, warp tile 32x32), K-chunk 32,
// 2-stage cp.async pipeline. Dynamic SMEM 61,440 B.
// ---------------------------------------------------------------------------
struct TileArgs {
    const bf16 *Ahi, *Alo, *Whi, *Wlo;
    const float* bias;   // may be null
    const float* add;    // may be null
    int ldadd;
    float* C;            // may be null
    int ldc;
    bf16 *Chi, *Clo;     // may be null
};

__device__ __forceinline__ void ldsm4(uint32_t* r, uint32_t addr) {
    asm volatile("ldmatrix.sync.aligned.m8n8.x4.shared.b16 {%0,%1,%2,%3}, [%4];\n"
                 : "=r"(r[0]), "=r"(r[1]), "=r"(r[2]), "=r"(r[3]) : "r"(addr));
}

#define MMA16816(c, a, b) \
    asm volatile("mma.sync.aligned.m16n8k16.row.col.f32.bf16.bf16.f32 " \
                 "{%0,%1,%2,%3}, {%4,%5,%6,%7}, {%8,%9}, {%0,%1,%2,%3};\n" \
                 : "+f"((c)[0]), "+f"((c)[1]), "+f"((c)[2]), "+f"((c)[3]) \
                 : "r"((a)[0]), "r"((a)[1]), "r"((a)[2]), "r"((a)[3]), \
                   "r"((b)[0]), "r"((b)[1]))

#define CPA16(saddr, gptr) \
    asm volatile("cp.async.cg.shared.global [%0], [%1], 16;\n" \
                 :: "r"(saddr), "l"(gptr))
#define CP_COMMIT() asm volatile("cp.async.commit_group;\n")
#define CP_WAIT1()  asm volatile("cp.async.wait_group 1;\n")
#define CP_WAIT0()  asm volatile("cp.async.wait_group 0;\n")

#define SKE      40
#define STAGE_B  30720
#define SMEM2_B  (2 * STAGE_B)

__device__ void gemm_tile(const TileArgs& g, int bm, int bn, int K, int act)
{
    extern __shared__ bf16 smd[];
    const int tid = threadIdx.x;
    const int lane = tid & 31;
    const int wid = tid >> 5;
    const int wm = (wid & 3) * 32;
    const int wn = (wid >> 2) * 32;

    const uint32_t s0 = (uint32_t)__cvta_generic_to_shared(smd);

    const int ar0 = (0 * 256 + tid) >> 2, ac0 = (((0 * 256 + tid) & 3) << 3);
    const int ar1 = (1 * 256 + tid) >> 2, ac1 = (((1 * 256 + tid) & 3) << 3);
    const int wr = tid >> 2,              wc = ((tid & 3) << 3);

    const bf16* Ahi = g.Ahi + (size_t)bm * K;
    const bf16* Alo = g.Alo + (size_t)bm * K;
    const bf16* Whi = g.Whi + (size_t)bn * K;
    const bf16* Wlo = g.Wlo + (size_t)bn * K;

#define LOAD_STAGE(st, ko) do {                                               \
        const uint32_t sb_ = s0 + (uint32_t)(st) * STAGE_B;                   \
        CPA16(sb_ + (uint32_t)((ar0 * SKE + ac0) * 2),                        \
              Ahi + (size_t)ar0 * K + (ko) + ac0);                            \
        CPA16(sb_ + (uint32_t)((ar1 * SKE + ac1) * 2),                        \
              Ahi + (size_t)ar1 * K + (ko) + ac1);                            \
        CPA16(sb_ + (uint32_t)((5120 + ar0 * SKE + ac0) * 2),                 \
              Alo + (size_t)ar0 * K + (ko) + ac0);                            \
        CPA16(sb_ + (uint32_t)((5120 + ar1 * SKE + ac1) * 2),                 \
              Alo + (size_t)ar1 * K + (ko) + ac1);                            \
        CPA16(sb_ + (uint32_t)((10240 + wr * SKE + wc) * 2),                  \
              Whi + (size_t)wr * K + (ko) + wc);                              \
        CPA16(sb_ + (uint32_t)((12800 + wr * SKE + wc) * 2),                  \
              Wlo + (size_t)wr * K + (ko) + wc);                              \
        CP_COMMIT();                                                          \
    } while (0)

    const uint32_t aoffb0 = ((wm +  0 + (lane & 15)) * SKE + ((lane >> 4) << 3)) * 2;
    const uint32_t aoffb1 = ((wm + 16 + (lane & 15)) * SKE + ((lane >> 4) << 3)) * 2;
    const uint32_t boffb0 = ((wn +  0 + (lane & 7) + ((lane >> 4) << 3)) * SKE +
                             (((lane >> 3) & 1) << 3)) * 2;
    const uint32_t boffb1 = ((wn + 16 + (lane & 7) + ((lane >> 4) << 3)) * SKE +
                             (((lane >> 3) & 1) << 3)) * 2;

    float acc[2][4][4];
#pragma unroll
    for (int i = 0; i < 2; i++)
#pragma unroll
        for (int j = 0; j < 4; j++)
#pragma unroll
            for (int q = 0; q < 4; q++) acc[i][j][q] = 0.f;

    const int nkc = K >> 5;
    LOAD_STAGE(0, 0);
    if (nkc > 1) { LOAD_STAGE(1, 32); CP_WAIT1(); } else { CP_WAIT0(); }
    __syncthreads();

    for (int kc = 0; kc < nkc; kc++) {
        const int st = kc & 1;
        const uint32_t sb = s0 + (uint32_t)st * STAGE_B;
        const uint32_t sAhi = sb, sAlo = sb + 10240;
        const uint32_t sWhi = sb + 20480, sWlo = sb + 25600;

#pragma unroll
        for (int ks = 0; ks < 2; ks++) {
            const uint32_t kso = ks * 32;
            uint32_t Ah[2][4], Al[2][4], Bh[2][4], Bl[2][4];
            ldsm4(Ah[0], sAhi + aoffb0 + kso);
            ldsm4(Ah[1], sAhi + aoffb1 + kso);
            ldsm4(Al[0], sAlo + aoffb0 + kso);
            ldsm4(Al[1], sAlo + aoffb1 + kso);
            ldsm4(Bh[0], sWhi + boffb0 + kso);
            ldsm4(Bh[1], sWhi + boffb1 + kso);
            ldsm4(Bl[0], sWlo + boffb0 + kso);
            ldsm4(Bl[1], sWlo + boffb1 + kso);

#pragma unroll
            for (int mt = 0; mt < 2; mt++) {
#pragma unroll
                for (int nt = 0; nt < 4; nt++) {
                    uint32_t* bh = &Bh[nt >> 1][(nt & 1) * 2];
                    uint32_t* bl = &Bl[nt >> 1][(nt & 1) * 2];
                    MMA16816(acc[mt][nt], Ah[mt], bh);
                    MMA16816(acc[mt][nt], Ah[mt], bl);
                    MMA16816(acc[mt][nt], Al[mt], bh);
                }
            }
        }

        __syncthreads();
        if (kc + 2 < nkc) { LOAD_STAGE(st, (kc + 2) << 5); CP_WAIT1(); }
        else              { CP_WAIT0(); }
        __syncthreads();
    }

#pragma unroll
    for (int mt = 0; mt < 2; mt++) {
#pragma unroll
        for (int nt = 0; nt < 4; nt++) {
            const int col = bn + wn + nt * 8 + ((lane & 3) << 1);
            float b0 = 0.f, b1 = 0.f;
            if (g.bias) { b0 = g.bias[col]; b1 = g.bias[col + 1]; }
#pragma unroll
            for (int half = 0; half < 2; half++) {
                const int row = bm + wm + mt * 16 + (lane >> 2) + half * 8;
                float v0 = acc[mt][nt][half * 2 + 0] + b0;
                float v1 = acc[mt][nt][half * 2 + 1] + b1;
                if (g.add) {
                    v0 += g.add[(size_t)row * g.ldadd + col];
                    v1 += g.add[(size_t)row * g.ldadd + col + 1];
                }
                if (act) { v0 = fmaxf(v0, 0.f); v1 = fmaxf(v1, 0.f); }
                if (g.C) {
                    float2 o; o.x = v0; o.y = v1;
                    *(float2*)&g.C[(size_t)row * g.ldc + col] = o;
                }
                if (g.Chi) {
                    bf16 h0, l0, h1, l1;
                    split1(v0, h0, l0); split1(v1, h1, l1);
                    __nv_bfloat162 ph; ph.x = h0; ph.y = h1;
                    __nv_bfloat162 pl; pl.x = l0; pl.y = l1;
                    *(__nv_bfloat162*)&g.Chi[(size_t)row * g.ldc + col] = ph;
                    *(__nv_bfloat162*)&g.Clo[(size_t)row * g.ldc + col] = pl;
                }
            }
        }
    }
#undef LOAD_STAGE
}

// Standalone wrapper (precompute + output head)
__global__ __launch_bounds__(256) void mma_gemm2(TileArgs g0, TileArgs g1, int K, int act)
{
    const TileArgs g = blockIdx.z ? g1 : g0;
    gemm_tile(g, blockIdx.y * 128, blockIdx.x * 64, K, act);
}

// ---------------------------------------------------------------------------
// fp32 GEMM (P_attn only, N=96)
// ---------------------------------------------------------------------------
struct GemmArgs {
    const float* A; const float* W; const float* bias;
    const float* add; int ldadd; float* C; int ldc;
};

template<int TM, int TN, int RM, int RN>
__global__ void gemm_tpl(GemmArgs g0, GemmArgs g1, int lda, int ldw, int K, int act)
{
    constexpr int LA = TM / 32;
    constexpr int LW = TN / 32;

    __shared__ float As[2][16][TM + 4];
    __shared__ float Ws[2][16][TN + 4];

    const GemmArgs g = blockIdx.z ? g1 : g0;
    const int bm = blockIdx.y * TM;
    const int bn = blockIdx.x * TN;
    const int tid = threadIdx.x;
    const int tn = tid % (TN / RN);
    const int tm = tid / (TN / RN);

    float acc[RM][RN];
#pragma unroll
    for (int i = 0; i < RM; i++)
#pragma unroll
        for (int j = 0; j < RN; j++) acc[i][j] = 0.f;

    const float* Abase = g.A + (size_t)bm * lda;
    const float* Wbase = g.W + (size_t)bn * ldw;
    float4 pa[LA], pw[LW];

#pragma unroll
    for (int q = 0; q < LA; q++) {
        int idx = q * 128 + tid; int r = idx >> 2; int kq = (idx & 3) << 2;
        pa[q] = *(const float4*)(Abase + (size_t)r * lda + kq);
    }
#pragma unroll
    for (int q = 0; q < LW; q++) {
        int idx = q * 128 + tid; int r = idx >> 2; int kq = (idx & 3) << 2;
        pw[q] = *(const float4*)(Wbase + (size_t)r * ldw + kq);
    }
#pragma unroll
    for (int q = 0; q < LA; q++) {
        int idx = q * 128 + tid; int r = idx >> 2; int kq = (idx & 3) << 2;
        As[0][kq + 0][r] = pa[q].x; As[0][kq + 1][r] = pa[q].y;
        As[0][kq + 2][r] = pa[q].z; As[0][kq + 3][r] = pa[q].w;
    }
#pragma unroll
    for (int q = 0; q < LW; q++) {
        int idx = q * 128 + tid; int r = idx >> 2; int kq = (idx & 3) << 2;
        Ws[0][kq + 0][r] = pw[q].x; Ws[0][kq + 1][r] = pw[q].y;
        Ws[0][kq + 2][r] = pw[q].z; Ws[0][kq + 3][r] = pw[q].w;
    }
    __syncthreads();

    const int nb = K >> 4;
    for (int kb = 0; kb < nb; kb++) {
        const int buf = kb & 1;
        if (kb + 1 < nb) {
            const int k0 = (kb + 1) << 4;
#pragma unroll
            for (int q = 0; q < LA; q++) {
                int idx = q * 128 + tid; int r = idx >> 2; int kq = (idx & 3) << 2;
                pa[q] = *(const float4*)(Abase + (size_t)r * lda + k0 + kq);
            }
#pragma unroll
            for (int q = 0; q < LW; q++) {
                int idx = q * 128 + tid; int r = idx >> 2; int kq = (idx & 3) << 2;
                pw[q] = *(const float4*)(Wbase + (size_t)r * ldw + k0 + kq);
            }
        }
#pragma unroll
        for (int kk = 0; kk < 16; kk++) {
            float a[RM], b[RN];
#pragma unroll
            for (int i = 0; i < RM / 4; i++)
                *(float4*)(a + 4 * i) = *(const float4*)&As[buf][kk][tm * RM + 4 * i];
#pragma unroll
            for (int j = 0; j < RN / 4; j++)
                *(float4*)(b + 4 * j) = *(const float4*)&Ws[buf][kk][tn * RN + 4 * j];
#pragma unroll
            for (int i = 0; i < RM; i++)
#pragma unroll
                for (int j = 0; j < RN; j++)
                    acc[i][j] = fmaf(a[i], b[j], acc[i][j]);
        }
        if (kb + 1 < nb) {
            const int nxt = buf ^ 1;
#pragma unroll
            for (int q = 0; q < LA; q++) {
                int idx = q * 128 + tid; int r = idx >> 2; int kq = (idx & 3) << 2;
                As[nxt][kq + 0][r] = pa[q].x; As[nxt][kq + 1][r] = pa[q].y;
                As[nxt][kq + 2][r] = pa[q].z; As[nxt][kq + 3][r] = pa[q].w;
            }
#pragma unroll
            for (int q = 0; q < LW; q++) {
                int idx = q * 128 + tid; int r = idx >> 2; int kq = (idx & 3) << 2;
                Ws[nxt][kq + 0][r] = pw[q].x; Ws[nxt][kq + 1][r] = pw[q].y;
                Ws[nxt][kq + 2][r] = pw[q].z; Ws[nxt][kq + 3][r] = pw[q].w;
            }
            __syncthreads();
        }
    }

#pragma unroll
    for (int i = 0; i < RM; i++) {
        const int row = bm + tm * RM + i;
#pragma unroll
        for (int j = 0; j < RN; j++) {
            const int col = bn + tn * RN + j;
            float v = acc[i][j];
            if (g.bias) v += g.bias[col];
            if (g.add)  v += g.add[(size_t)row * g.ldadd + col];
            if (act)    v = fmaxf(v, 0.f);
            g.C[(size_t)row * g.ldc + col] = v;
        }
    }
}

// ---------------------------------------------------------------------------
// Persistent megakernel for the full 36-step recurrent loop.
// ---------------------------------------------------------------------------
struct MegaParams {
    const float* enc;
    const float* attn_Wh;    // attn_W + 1024, row stride KCAT
    const float* pattn;
    const float* pcomb;
    const float* b_ih0; const float* b_hh0;
    const float* b_ih1; const float* b_hh1;
    float* out_h;            // h0 rows at [0], h1 rows at [B_*H_]
    float* out_aw;
    float *gi0, *gh0, *gi1, *gh1;
    bf16 *we_hi, *we_lo, *xc_hi, *xc_lo;
    bf16 *h0_hi, *h0_lo, *h1_hi, *h1_lo;
    bf16 *hs_hi, *hs_lo;
    const bf16 *ch_hi, *ch_lo;
    const bf16 *wih0_hi, *wih0_lo, *whh0_hi, *whh0_lo;
    const bf16 *wih1_hi, *wih1_lo, *whh1_hi, *whh1_lo;
    int ncta;
};

__device__ __forceinline__ void gbar(int ncta)
{
    __syncthreads();
    if (threadIdx.x == 0) {
        __threadfence();
        unsigned my = *(volatile unsigned*)&g_gen;
        unsigned pos = atomicAdd(&g_cnt, 1u);
        if (pos == (unsigned)ncta - 1u) {
            atomicExch(&g_cnt, 0u);
            __threadfence();
            atomicAdd(&g_gen, 1u);
        } else {
            while (*(volatile unsigned*)&g_gen == my) { __nanosleep(64); }
        }
        __threadfence();
    }
    __syncthreads();
}

__global__ __launch_bounds__(256, 2) void mega_kernel(MegaParams p)
{
    extern __shared__ bf16 smd[];
    const int tid = threadIdx.x;
    const int lane = tid & 31;
    const int w = tid >> 5;
    float* h0base = p.out_h;
    float* h1base = p.out_h + (size_t)B_ * H_;

    for (int t = 0; t <= T_; t++) {
        // ---- Phase A: gate1 (finalize h1 of step t-1) + attention softmax
        {
            float* sh   = (float*)smd;        // [0,1024) h1 row
            float* slog = sh + 1024;          // [1024,1120) logits
            float* sred = slog + S_;          // 2 reduction slots

            for (int b = blockIdx.x; b < B_; b += gridDim.x) {
                __syncthreads();
                float* h1row = h1base + (size_t)b * H_;
                if (t > 0) {
                    const float* gib = p.gi1 + (size_t)b * G3;
                    const float* ghb = p.gh1 + (size_t)b * G3;
                    for (int j = tid; j < H_; j += 256) {
                        float r = sigmoidf_(gib[j] + ghb[j]);
                        float z = sigmoidf_(gib[H_ + j] + ghb[H_ + j]);
                        float n = tanhf(fmaf(r, ghb[2 * H_ + j], gib[2 * H_ + j]));
                        float h = h1row[j];
                        float hn = fmaf(z, h - n, n);
                        h1row[j] = hn;
                        sh[j] = hn;
                        bf16 hi, lo; split1(hn, hi, lo);
                        p.h1_hi[(size_t)b * H_ + j] = hi;
                        p.h1_lo[(size_t)b * H_ + j] = lo;
                        size_t o = ((size_t)b * T_ + (t - 1)) * H_ + j;
                        p.hs_hi[o] = hi; p.hs_lo[o] = lo;
                    }
                } else {
                    for (int j = tid; j < H_; j += 256) sh[j] = h1row[j];
                }
                __syncthreads();
                if (t == T_) continue;

                for (int s = w; s < S_; s += 8) {
                    const float* wr = p.attn_Wh + (size_t)s * KCAT;
                    float acc = 0.f;
#pragma unroll
                    for (int c = 0; c < 8; c++) {
                        int k = c * 128 + lane * 4;
                        float4 hv = *(const float4*)(sh + k);
                        float4 wv = *(const float4*)(wr + k);
                        acc = fmaf(hv.x, wv.x, acc); acc = fmaf(hv.y, wv.y, acc);
                        acc = fmaf(hv.z, wv.z, acc); acc = fmaf(hv.w, wv.w, acc);
                    }
#pragma unroll
                    for (int o = 16; o > 0; o >>= 1)
                        acc += __shfl_xor_sync(0xFFFFFFFFu, acc, o);
                    if (lane == 0)
                        slog[s] = acc + p.pattn[((size_t)b * T_ + t) * S_ + s];
                }
                __syncthreads();
                if (w == 0) {
                    float m = -1e30f;
                    for (int s = lane; s < S_; s += 32) m = fmaxf(m, slog[s]);
#pragma unroll
                    for (int o = 16; o > 0; o >>= 1)
                        m = fmaxf(m, __shfl_xor_sync(0xFFFFFFFFu, m, o));
                    if (lane == 0) sred[0] = m;
                }
                __syncthreads();
                if (tid < S_) slog[tid] = expf(slog[tid] - sred[0]);
                __syncthreads();
                if (w == 0) {
                    float s0 = 0.f;
                    for (int s = lane; s < S_; s += 32) s0 += slog[s];
#pragma unroll
                    for (int o = 16; o > 0; o >>= 1)
                        s0 += __shfl_xor_sync(0xFFFFFFFFu, s0, o);
                    if (lane == 0) sred[1] = s0;
                }
                __syncthreads();
                if (tid < S_)
                    p.out_aw[((size_t)b * T_ + t) * S_ + tid] = slog[tid] / sred[1];
            }
        }
        if (t == T_) break;
        gbar(p.ncta);

        // ---- Phase A2: wenc (1024 tiles of 256 cols)
        {
            float* saw = (float*)smd;
            for (int tl = blockIdx.x; tl < B_ * 4; tl += gridDim.x) {
                int b = tl >> 2;
                int hc = (tl & 3) << 8;
                __syncthreads();
                if (tid < S_)
                    saw[tid] = p.out_aw[((size_t)b * T_ + t) * S_ + tid];
                __syncthreads();
                const float* e = p.enc + (size_t)b * S_ * H_ + hc + tid;
                float acc = 0.f;
#pragma unroll 8
                for (int s = 0; s < S_; s++)
                    acc = fmaf(saw[s], e[(size_t)s * H_], acc);
                bf16 hi, lo; split1(acc, hi, lo);
                p.we_hi[(size_t)b * H_ + hc + tid] = hi;
                p.we_lo[(size_t)b * H_ + hc + tid] = lo;
            }
        }
        gbar(p.ncta);

        // ---- Phase B: xc GEMM (32 tiles)
        {
            TileArgs a{p.we_hi, p.we_lo, p.ch_hi, p.ch_lo, nullptr,
                       p.pcomb + (size_t)t * D_, T_ * D_,
                       nullptr, D_, p.xc_hi, p.xc_lo};
            for (int tl = blockIdx.x; tl < 32; tl += gridDim.x)
                gemm_tile(a, (tl >> 4) * 128, (tl & 15) * 64, D_, 1);
        }
        gbar(p.ncta);

        // ---- Phase C: GRU layer 0 GEMMs (192 tiles)
        {
            TileArgs gia{p.xc_hi, p.xc_lo, p.wih0_hi, p.wih0_lo, p.b_ih0,
                         nullptr, 0, p.gi0, G3, nullptr, nullptr};
            TileArgs gha{p.h0_hi, p.h0_lo, p.whh0_hi, p.whh0_lo, p.b_hh0,
                         nullptr, 0, p.gh0, G3, nullptr, nullptr};
            for (int tl = blockIdx.x; tl < 192; tl += gridDim.x) {
                int r = (tl >= 96) ? tl - 96 : tl;
                gemm_tile((tl >= 96) ? gha : gia, (r / 48) * 128, (r % 48) * 64, D_, 0);
            }
        }
        gbar(p.ncta);

        // ---- Phase D: gate0
        for (int i = blockIdx.x * 256 + tid; i < B_ * H_; i += gridDim.x * 256) {
            int b = i >> 10, j = i & 1023;
            const float* gib = p.gi0 + (size_t)b * G3;
            const float* ghb = p.gh0 + (size_t)b * G3;
            float r = sigmoidf_(gib[j] + ghb[j]);
            float z = sigmoidf_(gib[H_ + j] + ghb[H_ + j]);
            float n = tanhf(fmaf(r, ghb[2 * H_ + j], gib[2 * H_ + j]));
            float h = h0base[i];
            float hn = fmaf(z, h - n, n);
            h0base[i] = hn;
            bf16 hi, lo; split1(hn, hi, lo);
            p.h0_hi[i] = hi; p.h0_lo[i] = lo;
        }
        gbar(p.ncta);

        // ---- Phase E: GRU layer 1 GEMMs (192 tiles)
        {
            TileArgs gia{p.h0_hi, p.h0_lo, p.wih1_hi, p.wih1_lo, p.b_ih1,
                         nullptr, 0, p.gi1, G3, nullptr, nullptr};
            TileArgs gha{p.h1_hi, p.h1_lo, p.whh1_hi, p.whh1_lo, p.b_hh1,
                         nullptr, 0, p.gh1, G3, nullptr, nullptr};
            for (int tl = blockIdx.x; tl < 192; tl += gridDim.x) {
                int r = (tl >= 96) ? tl - 96 : tl;
                gemm_tile((tl >= 96) ? gha : gia, (r / 48) * 128, (r % 48) * 64, H_, 0);
            }
        }
        gbar(p.ncta);
    }
}

// ---------------------------------------------------------------------------
// Launch
// ---------------------------------------------------------------------------
static inline void* sym(const void* s) { void* p; cudaGetSymbolAddress(&p, s); return p; }

extern "C" void kernel_launch(void* const* d_in, const int* in_sizes, int n_in,
                              void* d_out, int out_size)
{
    const float* target  = (const float*)d_in[0];
    const float* hidden0 = (const float*)d_in[1];
    const float* enc     = (const float*)d_in[2];
    const float* attn_W  = (const float*)d_in[3];
    const float* attn_b  = (const float*)d_in[4];
    const float* comb_W  = (const float*)d_in[5];
    const float* comb_b  = (const float*)d_in[6];
    const float* W_ih    = (const float*)d_in[7];
    const float* W_hh    = (const float*)d_in[8];
    const float* b_ih    = (const float*)d_in[9];
    const float* b_hh    = (const float*)d_in[10];
    const float* out1_W  = (const float*)d_in[11];
    const float* out1_b  = (const float*)d_in[12];
    const float* out2_W  = (const float*)d_in[13];
    const float* out2_b  = (const float*)d_in[14];

    float* outp = (float*)d_out;
    float* out_y  = outp + OUT_Y;
    float* out_h  = outp + OUT_H;
    float* out_aw = outp + OUT_AW;

    float* pattn = (float*)sym(g_pattn);
    float* pcomb = (float*)sym(g_pcomb);

    bf16 *tgt_hi = (bf16*)sym(g_tgt_hi), *tgt_lo = (bf16*)sym(g_tgt_lo);
    bf16 *cx_hi = (bf16*)sym(g_combx_hi), *cx_lo = (bf16*)sym(g_combx_lo);
    bf16 *ch_hi = (bf16*)sym(g_combh_hi), *ch_lo = (bf16*)sym(g_combh_lo);
    bf16 *wih_hi = (bf16*)sym(g_wih_hi), *wih_lo = (bf16*)sym(g_wih_lo);
    bf16 *whh_hi = (bf16*)sym(g_whh_hi), *whh_lo = (bf16*)sym(g_whh_lo);
    bf16 *o1_hi = (bf16*)sym(g_o1_hi), *o1_lo = (bf16*)sym(g_o1_lo);
    bf16 *o2_hi = (bf16*)sym(g_o2_hi), *o2_lo = (bf16*)sym(g_o2_lo);
    bf16 *hs_hi = (bf16*)sym(g_hseq_hi), *hs_lo = (bf16*)sym(g_hseq_lo);
    bf16 *y_hi = (bf16*)sym(g_y_hi), *y_lo = (bf16*)sym(g_y_lo);

    static int attr_done = 0;
    if (!attr_done) {
        cudaFuncSetAttribute(mma_gemm2,
                             cudaFuncAttributeMaxDynamicSharedMemorySize, SMEM2_B);
        cudaFuncSetAttribute(mega_kernel,
                             cudaFuncAttributeMaxDynamicSharedMemorySize, SMEM2_B);
        attr_done = 1;
    }

    cudaMemcpyAsync(out_h, hidden0, (size_t)L_ * B_ * H_ * sizeof(float),
                    cudaMemcpyDeviceToDevice);

    float* h0 = out_h;
    float* h1 = out_h + (size_t)B_ * H_;

    // ---- startup: bf16 splits
    const int SB = 256;
    {
        int n;
        n = BT * D_;       split_kernel<<<(n + SB - 1) / SB, SB>>>(target, D_, 0, D_, tgt_hi, tgt_lo, n);
        n = D_ * D_;       split_kernel<<<(n + SB - 1) / SB, SB>>>(comb_W, KCAT, 0, D_, cx_hi, cx_lo, n);
        n = D_ * D_;       split_kernel<<<(n + SB - 1) / SB, SB>>>(comb_W, KCAT, D_, D_, ch_hi, ch_lo, n);
        n = L_ * G3 * D_;  split_kernel<<<(n + SB - 1) / SB, SB>>>(W_ih, D_, 0, D_, wih_hi, wih_lo, n);
        n = L_ * G3 * H_;  split_kernel<<<(n + SB - 1) / SB, SB>>>(W_hh, H_, 0, H_, whh_hi, whh_lo, n);
        n = D_ * H_;       split_kernel<<<(n + SB - 1) / SB, SB>>>(out1_W, H_, 0, H_, o1_hi, o1_lo, n);
        n = D_ * D_;       split_kernel<<<(n + SB - 1) / SB, SB>>>(out2_W, D_, 0, D_, o2_hi, o2_lo, n);
        n = B_ * H_;       split_kernel<<<(n + SB - 1) / SB, SB>>>(h0, H_, 0, H_,
                               (bf16*)sym(g_h0_hi), (bf16*)sym(g_h0_lo), n);
        n = B_ * H_;       split_kernel<<<(n + SB - 1) / SB, SB>>>(h1, H_, 0, H_,
                               (bf16*)sym(g_h1_hi), (bf16*)sym(g_h1_lo), n);
    }

    // ---- precompute target-dependent halves
    {
        TileArgs a{tgt_hi, tgt_lo, cx_hi, cx_lo, comb_b, nullptr, 0,
                   pcomb, D_, nullptr, nullptr};
        mma_gemm2<<<dim3(D_ / 64, BT / 128, 1), 256, SMEM2_B>>>(a, a, D_, 0);
    }
    {
        GemmArgs a{target, attn_W, attn_b, nullptr, 0, pattn, S_};
        gemm_tpl<64, 32, 4, 4><<<dim3(S_ / 32, BT / 64, 1), 128>>>(a, a, D_, KCAT, 1024, 0);
    }

    // ---- persistent megakernel: the whole 36-step loop
    {
        int nsm = 0;
        cudaDeviceGetAttribute(&nsm, cudaDevAttrMultiProcessorCount, 0);
        int bpm = 0;
        cudaOccupancyMaxActiveBlocksPerMultiprocessor(&bpm, mega_kernel, 256, SMEM2_B);
        if (bpm < 1) bpm = 1;
        int ncta = nsm * bpm;
        if (ncta > 1024) ncta = 1024;

        MegaParams p;
        p.enc = enc;
        p.attn_Wh = attn_W + 1024;
        p.pattn = pattn;
        p.pcomb = pcomb;
        p.b_ih0 = b_ih;        p.b_hh0 = b_hh;
        p.b_ih1 = b_ih + G3;   p.b_hh1 = b_hh + G3;
        p.out_h = out_h;
        p.out_aw = out_aw;
        p.gi0 = (float*)sym(g_gi0); p.gh0 = (float*)sym(g_gh0);
        p.gi1 = (float*)sym(g_gi1); p.gh1 = (float*)sym(g_gh1);
        p.we_hi = (bf16*)sym(g_we_hi); p.we_lo = (bf16*)sym(g_we_lo);
        p.xc_hi = (bf16*)sym(g_xc_hi); p.xc_lo = (bf16*)sym(g_xc_lo);
        p.h0_hi = (bf16*)sym(g_h0_hi); p.h0_lo = (bf16*)sym(g_h0_lo);
        p.h1_hi = (bf16*)sym(g_h1_hi); p.h1_lo = (bf16*)sym(g_h1_lo);
        p.hs_hi = hs_hi; p.hs_lo = hs_lo;
        p.ch_hi = ch_hi; p.ch_lo = ch_lo;
        p.wih0_hi = wih_hi;                    p.wih0_lo = wih_lo;
        p.whh0_hi = whh_hi;                    p.whh0_lo = whh_lo;
        p.wih1_hi = wih_hi + (size_t)G3 * D_;  p.wih1_lo = wih_lo + (size_t)G3 * D_;
        p.whh1_hi = whh_hi + (size_t)G3 * H_;  p.whh1_lo = whh_lo + (size_t)G3 * H_;
        p.ncta = ncta;

        mega_kernel<<<ncta, 256, SMEM2_B>>>(p);
    }

    // ---- output head, batched over all 36 steps
    {
        TileArgs a{hs_hi, hs_lo, o1_hi, o1_lo, out1_b, nullptr, 0,
                   nullptr, D_, y_hi, y_lo};
        mma_gemm2<<<dim3(D_ / 64, BT / 128, 1), 256, SMEM2_B>>>(a, a, H_, 0);
    }
    {
        TileArgs a{y_hi, y_lo, o2_hi, o2_lo, out2_b, nullptr, 0,
                   out_y, D_, nullptr, nullptr};
        mma_gemm2<<<dim3(D_ / 64, BT / 128, 1), 256, SMEM2_B>>>(a, a, D_, 0);
    }
}